// round 16
// baseline (speedup 1.0000x reference)
#include <cuda_runtime.h>
#include <cuda_fp16.h>
#include <math.h>
#include <stdint.h>

#define NPTS 4096
#define NB 8
#define KNN 32
#define ROWS_TOTAL (NB*NPTS)   // 32768
#define FULLMASK 0xffffffffu

typedef unsigned long long u64;

// ---------------- scratch (device globals; no allocation) ----------------
__device__ float g_D[(size_t)NB*NPTS*NPTS];                      // 512 MB keys (layers 2/3)
__device__ __align__(16) float4 g_xp[ROWS_TOTAL];                // layer1: (x0,x1,x2,sq)
__device__ __align__(16) __half g_xh[(size_t)ROWS_TOTAL*64];
__device__ __align__(16) __half g_xl[(size_t)ROWS_TOTAL*64];
__device__ __align__(16) float g_sq[ROWS_TOTAL];
__device__ float g_q[ROWS_TOTAL*64];
__device__ float g_v[ROWS_TOTAL*64];
__device__ float g_y[ROWS_TOTAL*64];
__device__ float g_scale[64];
__device__ float g_shift[64];
__device__ float g_part[256*64];
__device__ float g_partsq[256*64];
__device__ float g_lpart[96];

// ---------------- small helpers ----------------
__device__ __forceinline__ unsigned ordf(float f) {
    unsigned u = __float_as_uint(f);
    return u ^ (unsigned)(((int)u >> 31) | 0x80000000);
}
__device__ __forceinline__ float iordf(unsigned u) {
    unsigned v = (u & 0x80000000u) ? (u ^ 0x80000000u) : ~u;
    return __uint_as_float(v);
}
__device__ __forceinline__ void cpasync16(uint32_t dst, const void* src) {
    asm volatile("cp.async.cg.shared.global [%0], [%1], 16;" :: "r"(dst), "l"(src));
}
__device__ __forceinline__ void cp_commit() {
    asm volatile("cp.async.commit_group;");
}
template<int N>
__device__ __forceinline__ void cp_wait() {
    asm volatile("cp.async.wait_group %0;" :: "n"(N));
}
__device__ __forceinline__ float4 ldcs4(const float4* p) {
    float4 v;
    asm volatile("ld.global.cs.v4.f32 {%0,%1,%2,%3}, [%4];"
        : "=f"(v.x), "=f"(v.y), "=f"(v.z), "=f"(v.w) : "l"(p));
    return v;
}
__device__ __forceinline__ void stcs2(float* p, float2 v) {
    asm volatile("st.global.cs.v2.f32 [%0], {%1,%2};" :: "l"(p), "f"(v.x), "f"(v.y));
}
__device__ __forceinline__ void stcs1(float* p, float v) {
    asm volatile("st.global.cs.f32 [%0], %1;" :: "l"(p), "f"(v));
}

#define SWZ128(off) ((off) ^ (((off) >> 3) & 0x70))

#define LDSM_X4(r, addr) \
    asm volatile("ldmatrix.sync.aligned.m8n8.x4.shared.b16 {%0,%1,%2,%3}, [%4];" \
        : "=r"((r)[0]), "=r"((r)[1]), "=r"((r)[2]), "=r"((r)[3]) : "r"(addr))
#define LDSM_X2(r, addr) \
    asm volatile("ldmatrix.sync.aligned.m8n8.x2.shared.b16 {%0,%1}, [%2];" \
        : "=r"((r)[0]), "=r"((r)[1]) : "r"(addr))
#define MMA_F16(d0,d1,d2,d3,a,b0,b1) \
    asm volatile("mma.sync.aligned.m16n8k16.row.col.f32.f16.f16.f32 " \
        "{%0,%1,%2,%3}, {%4,%5,%6,%7}, {%8,%9}, {%0,%1,%2,%3};" \
        : "+f"(d0), "+f"(d1), "+f"(d2), "+f"(d3) \
        : "r"((a)[0]), "r"((a)[1]), "r"((a)[2]), "r"((a)[3]), "r"(b0), "r"(b1))

// ---------------- layer-1 prep (f=3) ----------------
__global__ __launch_bounds__(128) void prep1_kernel(
    const float* __restrict__ x, const float* __restrict__ W,
    const float* __restrict__ b)
{
    __shared__ float sW[6*64];
    __shared__ float sb[64];
    int t = threadIdx.x;
    for (int i = t; i < 6*64; i += 128) sW[i] = W[i];
    if (t < 64) sb[t] = b[t];
    __syncthreads();
    int row = blockIdx.x * 128 + t;
    float x0 = x[row*3+0], x1 = x[row*3+1], x2 = x[row*3+2];
    float sq = x0*x0 + x1*x1 + x2*x2;
    g_xp[row] = make_float4(x0, x1, x2, sq);
    #pragma unroll 4
    for (int o = 0; o < 64; o++) {
        float s1 = x0*sW[0*64+o] + x1*sW[1*64+o] + x2*sW[2*64+o];
        float s2 = x0*sW[3*64+o] + x1*sW[4*64+o] + x2*sW[5*64+o];
        g_q[row*64+o] = s1 - s2 + sb[o];
        g_v[row*64+o] = s2;
    }
}

// ------- layers 2/3 prep: ReLU+BN on y -> xh/xl, sq, q, v (f=64) -------
// 2 threads per row: halved serial FMA chain, doubled warp parallelism.
template<int O>
__global__ __launch_bounds__(256) void prepbn_kernel(
    const float* __restrict__ W, const float* __restrict__ b)
{
    __shared__ float sW[128*O];
    __shared__ float sb[O];
    __shared__ float ssc[64], ssh[64];
    int t = threadIdx.x;
    for (int i = t; i < 128*O; i += 256) sW[i] = W[i];
    if (t < O) sb[t] = b[t];
    if (t < 64) { ssc[t] = g_scale[t]; ssh[t] = g_shift[t]; }
    __syncthreads();
    int row = blockIdx.x * 128 + (t >> 1);
    int half = t & 1;
    float xr[64];
    float s = 0.f;
    #pragma unroll
    for (int f = 0; f < 64; f++) {
        float yy = g_y[(size_t)row*64 + f];
        float xn = ssc[f]*fmaxf(yy, 0.f) + ssh[f];
        xr[f] = xn;
        s += xn*xn;
    }
    // split the xh/xl writes between the two threads of this row
    #pragma unroll
    for (int f = half*32; f < half*32 + 32; f++) {
        __half h = __float2half(xr[f]);
        g_xh[(size_t)row*64 + f] = h;
        g_xl[(size_t)row*64 + f] = __float2half(xr[f] - __half2float(h));
    }
    if (half == 0) g_sq[row] = s;
    // interleaved o-split (identical per-o FMA order as before)
    for (int o = half; o < O; o += 2) {
        float s1 = 0.f, s2 = 0.f;
        #pragma unroll
        for (int f = 0; f < 64; f++) {
            s1 += xr[f]*sW[f*O + o];
            s2 += xr[f]*sW[(64+f)*O + o];
        }
        g_q[(size_t)row*O + o] = s1 - s2 + sb[o];
        g_v[(size_t)row*O + o] = s2;
    }
}

// =============== symmetric tile distance kernel (layers 2/3) ===============
// Block = one (ti, tj) tile pair with ti <= tj (528 pairs) x batch.
static constexpr uint32_t SOFF_AHI = 0;          // 16 KB (i-tile hi)
static constexpr uint32_t SOFF_ALO = 16384;      // 16 KB (i-tile lo)
static constexpr uint32_t SOFF_BHI = 32768;      // 16 KB (j-tile hi)
static constexpr uint32_t SOFF_BLO = 49152;      // 16 KB (j-tile lo)
static constexpr uint32_t SOFF_SQI = 65536;      // 512 B
static constexpr uint32_t SOFF_SQJ = 66048;      // 512 B
static constexpr int DSMEM_SYM     = 66560 + 1024;

template<int NK>   // k16 steps: 4 for f=64
__global__ __launch_bounds__(256, 3) void distsym_kernel(
    const __half* __restrict__ XH, const __half* __restrict__ XL,
    const float* __restrict__ SQ, float* __restrict__ D)
{
    extern __shared__ char smraw[];
    uint32_t sm0  = (uint32_t)__cvta_generic_to_shared(smraw);
    uint32_t base = (sm0 + 1023) & ~1023u;
    char* gen = smraw + (base - sm0);

    const int t = threadIdx.x;
    const int w = t >> 5;
    const int lane = t & 31;
    const int batch = blockIdx.y;

    int p = blockIdx.x, ti = 0;
    #pragma unroll 1
    while (p >= 32 - ti) { p -= 32 - ti; ti++; }
    const int tj = ti + p;
    const int i0 = ti * 128, j0 = tj * 128;
    const bool diag = (ti == tj);

    const __half* XHb = XH + (size_t)batch * NPTS * 64;
    const __half* XLb = XL + (size_t)batch * NPTS * 64;
    const float* SQb = SQ + batch * NPTS;
    float* Db = D + (size_t)batch * NPTS * NPTS;

    #pragma unroll
    for (int k = 0; k < 8; k++) {
        int idx = t + 256*k;
        int which = idx >> 10;
        int r = (idx >> 3) & 127;
        int c8 = idx & 7;
        uint32_t sw = SWZ128((uint32_t)(r*128 + c8*16));
        cpasync16(base + (which ? SOFF_ALO : SOFF_AHI) + sw,
                  (which ? XLb : XHb) + (size_t)(i0 + r)*64 + c8*8);
        cpasync16(base + (which ? SOFF_BLO : SOFF_BHI) + sw,
                  (which ? XLb : XHb) + (size_t)(j0 + r)*64 + c8*8);
    }
    if (t < 32) cpasync16(base + SOFF_SQI + t*16, SQb + i0 + t*4);
    else if (t < 64) cpasync16(base + SOFF_SQJ + (t-32)*16, SQb + j0 + (t-32)*4);
    cp_commit();
    cp_wait<0>();
    __syncthreads();

    uint32_t ahi[NK][4], alo[NK][4];
    {
        int arow = w*16 + (lane & 15);
        int acolb = (lane >> 4) * 16;
        #pragma unroll
        for (int ks = 0; ks < NK; ks++) {
            uint32_t off = (uint32_t)(arow*128 + ks*32 + acolb);
            LDSM_X4(ahi[ks], base + SOFF_AHI + SWZ128(off));
            LDSM_X4(alo[ks], base + SOFF_ALO + SWZ128(off));
        }
    }

    const int brl = lane & 15;
    const int rr = lane >> 2;
    const int irow  = i0 + w*16 + rr;
    const float* s_sqi = (const float*)(gen + SOFF_SQI);
    const float2* sqjp = (const float2*)(gen + SOFF_SQJ);
    const float sqi0 = s_sqi[w*16 + rr];
    const float sqi8 = s_sqi[w*16 + rr + 8];

    #pragma unroll
    for (int nb = 0; nb < 16; nb++) {
        float d0 = 0.f, d1 = 0.f, d2 = 0.f, d3 = 0.f;
        #pragma unroll
        for (int ks = 0; ks < NK; ks++) {
            uint32_t off = (uint32_t)((nb*8 + (brl & 7))*128 + ks*32
                                      + ((brl >> 3) & 1)*16);
            uint32_t bh[2], bl[2];
            LDSM_X2(bh, base + SOFF_BHI + SWZ128(off));
            LDSM_X2(bl, base + SOFF_BLO + SWZ128(off));
            MMA_F16(d0, d1, d2, d3, ahi[ks], bh[0], bh[1]);
            MMA_F16(d0, d1, d2, d3, ahi[ks], bl[0], bl[1]);
            MMA_F16(d0, d1, d2, d3, alo[ks], bh[0], bh[1]);
        }
        float2 sq2 = sqjp[nb*4 + (lane & 3)];
        int j = j0 + nb*8 + 2*(lane & 3);
        float2 o0, o1;
        o0.x = fmaf(d0, -2.f, sq2.x); o0.y = fmaf(d1, -2.f, sq2.y);
        o1.x = fmaf(d2, -2.f, sq2.x); o1.y = fmaf(d3, -2.f, sq2.y);
        stcs2(&Db[(size_t)irow*NPTS + j], o0);
        stcs2(&Db[(size_t)(irow + 8)*NPTS + j], o1);
        if (!diag) {
            stcs1(&Db[(size_t)j*NPTS + irow],           fmaf(d0, -2.f, sqi0));
            stcs1(&Db[(size_t)(j+1)*NPTS + irow],       fmaf(d1, -2.f, sqi0));
            stcs1(&Db[(size_t)j*NPTS + irow + 8],       fmaf(d2, -2.f, sqi8));
            stcs1(&Db[(size_t)(j+1)*NPTS + irow + 8],   fmaf(d3, -2.f, sqi8));
        }
    }
}

// ====== layer-1 fused select: on-the-fly f=3 keys + exact top-32 + gather ======
template<int O>
__global__ __launch_bounds__(256) void select1_kernel(
    const float4* __restrict__ XP, const float* __restrict__ V,
    const float* __restrict__ Q, float* __restrict__ OUT)
{
    const int wid = threadIdx.x >> 5;
    const int lane = threadIdx.x & 31;
    const int row = blockIdx.x * 8 + wid;          // 0..32767
    const int b = row >> 12;
    const float4* XPb = XP + b * NPTS;

    float4 xi = __ldg(&XPb[row & 4095]);
    const float a0 = -2.f * xi.x, a1 = -2.f * xi.y, a2 = -2.f * xi.z;

    float thr = INFINITY;
    unsigned svalu = 0xFF800000u;   // ordf(+inf)
    int sidx = 0, vlane = 0;

    for (int it = 0; it < 8; it++) {
        #pragma unroll
        for (int q = 0; q < 4; q++) {
            const int jb0 = it*512 + q*128;
            float4 p0 = __ldg(&XPb[jb0 + 4*lane + 0]);
            float4 p1 = __ldg(&XPb[jb0 + 4*lane + 1]);
            float4 p2 = __ldg(&XPb[jb0 + 4*lane + 2]);
            float4 p3 = __ldg(&XPb[jb0 + 4*lane + 3]);
            float4 vv;
            vv.x = fmaf(a0, p0.x, fmaf(a1, p0.y, fmaf(a2, p0.z, p0.w)));
            vv.y = fmaf(a0, p1.x, fmaf(a1, p1.y, fmaf(a2, p1.z, p1.w)));
            vv.z = fmaf(a0, p2.x, fmaf(a1, p2.y, fmaf(a2, p2.z, p2.w)));
            vv.w = fmaf(a0, p3.x, fmaf(a1, p3.y, fmaf(a2, p3.z, p3.w)));
            float rmin = fminf(fminf(vv.x, vv.y), fminf(vv.z, vv.w));
            if (__ballot_sync(FULLMASK, rmin < thr)) {
                #pragma unroll
                for (int s = 0; s < 4; s++) {
                    float key = (s==0) ? vv.x : (s==1) ? vv.y : (s==2) ? vv.z : vv.w;
                    unsigned m = __ballot_sync(FULLMASK, key < thr);
                    while (m) {
                        int src = __ffs(m) - 1; m &= m - 1;
                        float kc = __shfl_sync(FULLMASK, key, src);
                        if (kc < thr) {
                            if (lane == vlane) { svalu = ordf(kc); sidx = jb0 + src*4 + s; }
                            unsigned tu = __reduce_max_sync(FULLMASK, svalu);
                            vlane = __ffs(__ballot_sync(FULLMASK, svalu == tu)) - 1;
                            thr = iordf(tu);
                        }
                    }
                }
            }
        }
    }

    const int bb = b * NPTS;
    float m0 = -INFINITY, m1 = -INFINITY;
    #pragma unroll 4
    for (int s = 0; s < 32; s++) {
        int js = __shfl_sync(FULLMASK, sidx, s);
        const float* vp = V + (size_t)(bb + js) * 64;
        m0 = fmaxf(m0, vp[lane]);
        m1 = fmaxf(m1, vp[lane + 32]);
    }
    OUT[(size_t)row*64 + lane]      = Q[(size_t)row*64 + lane] + m0;
    OUT[(size_t)row*64 + lane + 32] = Q[(size_t)row*64 + lane + 32] + m1;
}

// ====== warp-per-row exact top-32 streaming select + v-gather (layers 2/3) ======
template<int O>
__global__ __launch_bounds__(256) void select_kernel(
    const float* __restrict__ D, const float* __restrict__ V,
    const float* __restrict__ Q, float* __restrict__ OUT)
{
    const int wid = threadIdx.x >> 5;
    const int lane = threadIdx.x & 31;
    const int row = blockIdx.x * 8 + wid;          // 0..32767
    const int b = row >> 12;
    const float4* Drow = (const float4*)(D + (size_t)b*NPTS*NPTS
                                           + (size_t)(row & 4095)*NPTS);

    float thr = INFINITY;
    unsigned svalu = 0xFF800000u;   // ordf(+inf)
    int sidx = 0, vlane = 0;

    for (int it = 0; it < 8; it++) {
        float4 vq[4];
        #pragma unroll
        for (int q = 0; q < 4; q++) vq[q] = ldcs4(&Drow[it*128 + q*32 + lane]);
        #pragma unroll
        for (int q = 0; q < 4; q++) {
            float4 vv = vq[q];
            const int jb0 = it*512 + q*128;
            float rmin = fminf(fminf(vv.x, vv.y), fminf(vv.z, vv.w));
            if (__ballot_sync(FULLMASK, rmin < thr)) {
                #pragma unroll
                for (int s = 0; s < 4; s++) {
                    float key = (s==0) ? vv.x : (s==1) ? vv.y : (s==2) ? vv.z : vv.w;
                    unsigned m = __ballot_sync(FULLMASK, key < thr);
                    while (m) {
                        int src = __ffs(m) - 1; m &= m - 1;
                        float kc = __shfl_sync(FULLMASK, key, src);
                        if (kc < thr) {
                            if (lane == vlane) { svalu = ordf(kc); sidx = jb0 + src*4 + s; }
                            unsigned tu = __reduce_max_sync(FULLMASK, svalu);
                            vlane = __ffs(__ballot_sync(FULLMASK, svalu == tu)) - 1;
                            thr = iordf(tu);
                        }
                    }
                }
            }
        }
    }

    const int bb = b * NPTS;
    if (O == 64) {
        float m0 = -INFINITY, m1 = -INFINITY;
        #pragma unroll 4
        for (int s = 0; s < 32; s++) {
            int js = __shfl_sync(FULLMASK, sidx, s);
            const float* vp = V + (size_t)(bb + js) * 64;
            m0 = fmaxf(m0, vp[lane]);
            m1 = fmaxf(m1, vp[lane + 32]);
        }
        OUT[(size_t)row*64 + lane]      = Q[(size_t)row*64 + lane] + m0;
        OUT[(size_t)row*64 + lane + 32] = Q[(size_t)row*64 + lane + 32] + m1;
    } else {
        float m0 = -INFINITY;
        for (int s = 0; s < 32; s++) {
            int js = __shfl_sync(FULLMASK, sidx, s);
            if (lane < O) m0 = fmaxf(m0, V[(size_t)(bb + js) * O + lane]);
        }
        if (lane < O) OUT[(size_t)row*O + lane] = Q[(size_t)row*O + lane] + m0;
    }
}

// ---------------- BN stats ----------------
__global__ __launch_bounds__(256) void bnred_kernel()
{
    __shared__ float ps[256], pss[256];
    int t = threadIdx.x, c = t & 63, g = t >> 6;
    int row0 = blockIdx.x * 128;
    float s = 0.f, ss = 0.f;
    for (int r = g; r < 128; r += 4) {
        float a = fmaxf(g_y[(size_t)(row0+r)*64 + c], 0.f);
        s += a; ss += a*a;
    }
    ps[t] = s; pss[t] = ss;
    __syncthreads();
    if (t < 64) {
        g_part[blockIdx.x*64 + t]   = ps[t]  + ps[t+64]  + ps[t+128]  + ps[t+192];
        g_partsq[blockIdx.x*64 + t] = pss[t] + pss[t+64] + pss[t+128] + pss[t+192];
    }
}

__global__ __launch_bounds__(256) void bnfin_kernel(
    const float* __restrict__ gamma, const float* __restrict__ beta)
{
    __shared__ float s1[256], s2[256];
    int t = threadIdx.x, c = t & 63, g = t >> 6;
    float s = 0.f, ss = 0.f;
    for (int p = g; p < 256; p += 4) { s += g_part[p*64 + c]; ss += g_partsq[p*64 + c]; }
    s1[t] = s; s2[t] = ss;
    __syncthreads();
    if (t < 64) {
        float S  = s1[t] + s1[t+64] + s1[t+128] + s1[t+192];
        float SS = s2[t] + s2[t+64] + s2[t+128] + s2[t+192];
        const float inv = 1.f / 32768.f;
        float mean = S * inv;
        float var = SS * inv - mean*mean;
        if (var < 0.f) var = 0.f;
        float sc = gamma[t] * rsqrtf(var + 1e-5f);
        g_scale[t] = sc;
        g_shift[t] = beta[t] - mean*sc;
    }
}

// ---------------- loss ----------------
__global__ __launch_bounds__(256) void lossred_kernel(
    const float* __restrict__ h, const float* __restrict__ tgt)
{
    __shared__ float ps[256];
    int t = threadIdx.x;
    int base = blockIdx.x * 1024;
    float s = 0.f;
    for (int k = t; k < 1024; k += 256) {
        float d = h[base + k] - tgt[base + k];
        s += d*d;
    }
    ps[t] = s; __syncthreads();
    for (int off = 128; off > 0; off >>= 1) {
        if (t < off) ps[t] += ps[t + off];
        __syncthreads();
    }
    if (t == 0) g_lpart[blockIdx.x] = ps[0];
}

__global__ __launch_bounds__(128) void lossfin_kernel(float* __restrict__ out_loss)
{
    __shared__ float buf[128];
    int t = threadIdx.x;
    buf[t] = (t < 96) ? g_lpart[t] : 0.f;
    __syncthreads();
    for (int off = 64; off > 0; off >>= 1) {
        if (t < off) buf[t] += buf[t + off];
        __syncthreads();
    }
    if (t == 0) *out_loss = buf[0] / 98304.0f;
}

// ---------------- driver ----------------
extern "C" void kernel_launch(void* const* d_in, const int* in_sizes, int n_in,
                              void* d_out, int out_size)
{
    const float* x   = (const float*)d_in[0];
    const float* tgt = (const float*)d_in[1];
    const float* W1  = (const float*)d_in[2];
    const float* b1  = (const float*)d_in[3];
    const float* g1  = (const float*)d_in[4];
    const float* be1 = (const float*)d_in[5];
    const float* W2  = (const float*)d_in[6];
    const float* b2  = (const float*)d_in[7];
    const float* g2  = (const float*)d_in[8];
    const float* be2 = (const float*)d_in[9];
    const float* W3  = (const float*)d_in[10];
    const float* b3  = (const float*)d_in[11];
    float* out = (float*)d_out;

    float *p_D, *p_sq, *p_q, *p_v, *p_y;
    float4* p_xp;
    __half *p_xh, *p_xl;
    cudaGetSymbolAddress((void**)&p_D,  g_D);
    cudaGetSymbolAddress((void**)&p_xp, g_xp);
    cudaGetSymbolAddress((void**)&p_sq, g_sq);
    cudaGetSymbolAddress((void**)&p_q,  g_q);
    cudaGetSymbolAddress((void**)&p_v,  g_v);
    cudaGetSymbolAddress((void**)&p_y,  g_y);
    cudaGetSymbolAddress((void**)&p_xh, g_xh);
    cudaGetSymbolAddress((void**)&p_xl, g_xl);

    cudaFuncSetAttribute(distsym_kernel<4>,
                         cudaFuncAttributeMaxDynamicSharedMemorySize, DSMEM_SYM);

    dim3 sgrid(528, NB);

    // ----- layer 1 (f=3 -> 64): no D materialization, keys on the fly -----
    prep1_kernel<<<256, 128>>>(x, W1, b1);
    select1_kernel<64><<<4096, 256>>>(p_xp, p_v, p_q, p_y);
    bnred_kernel<<<256, 256>>>();
    bnfin_kernel<<<1, 256>>>(g1, be1);

    // ----- layer 2 (f=64 -> 64) -----
    prepbn_kernel<64><<<256, 256>>>(W2, b2);
    distsym_kernel<4><<<sgrid, 256, DSMEM_SYM>>>(p_xh, p_xl, p_sq, p_D);
    select_kernel<64><<<4096, 256>>>(p_D, p_v, p_q, p_y);
    bnred_kernel<<<256, 256>>>();
    bnfin_kernel<<<1, 256>>>(g2, be2);

    // ----- layer 3 (f=64 -> 3), h straight to d_out -----
    prepbn_kernel<3><<<256, 256>>>(W3, b3);
    distsym_kernel<4><<<sgrid, 256, DSMEM_SYM>>>(p_xh, p_xl, p_sq, p_D);
    select_kernel<3><<<4096, 256>>>(p_D, p_v, p_q, out);

    // ----- loss -----
    lossred_kernel<<<96, 256>>>(out, tgt);
    lossfin_kernel<<<1, 128>>>(out + (out_size - 1));
}

// round 17
// speedup vs baseline: 1.0061x; 1.0061x over previous
#include <cuda_runtime.h>
#include <cuda_fp16.h>
#include <math.h>
#include <stdint.h>

#define NPTS 4096
#define NB 8
#define KNN 32
#define ROWS_TOTAL (NB*NPTS)   // 32768
#define FULLMASK 0xffffffffu

typedef unsigned long long u64;

// ---------------- scratch (device globals; no allocation) ----------------
__device__ float g_D[(size_t)NB*NPTS*NPTS];                      // 512 MB keys (layers 2/3)
__device__ __align__(16) float4 g_xp[ROWS_TOTAL];                // layer1: (x0,x1,x2,sq)
__device__ __align__(16) __half g_xh[(size_t)ROWS_TOTAL*64];
__device__ __align__(16) __half g_xl[(size_t)ROWS_TOTAL*64];
__device__ __align__(16) float g_sq[ROWS_TOTAL];
__device__ float g_q[ROWS_TOTAL*64];
__device__ float g_v[ROWS_TOTAL*64];
__device__ float g_y[ROWS_TOTAL*64];
__device__ float g_scale[64];
__device__ float g_shift[64];
__device__ float g_part[256*64];
__device__ float g_partsq[256*64];
__device__ float g_lpart[96];

// ---------------- small helpers ----------------
__device__ __forceinline__ unsigned ordf(float f) {
    unsigned u = __float_as_uint(f);
    return u ^ (unsigned)(((int)u >> 31) | 0x80000000);
}
__device__ __forceinline__ float iordf(unsigned u) {
    unsigned v = (u & 0x80000000u) ? (u ^ 0x80000000u) : ~u;
    return __uint_as_float(v);
}
__device__ __forceinline__ void cpasync16(uint32_t dst, const void* src) {
    asm volatile("cp.async.cg.shared.global [%0], [%1], 16;" :: "r"(dst), "l"(src));
}
__device__ __forceinline__ void cp_commit() {
    asm volatile("cp.async.commit_group;");
}
template<int N>
__device__ __forceinline__ void cp_wait() {
    asm volatile("cp.async.wait_group %0;" :: "n"(N));
}
__device__ __forceinline__ float4 ldcs4(const float4* p) {
    float4 v;
    asm volatile("ld.global.cs.v4.f32 {%0,%1,%2,%3}, [%4];"
        : "=f"(v.x), "=f"(v.y), "=f"(v.z), "=f"(v.w) : "l"(p));
    return v;
}
__device__ __forceinline__ void stcs2(float* p, float2 v) {
    asm volatile("st.global.cs.v2.f32 [%0], {%1,%2};" :: "l"(p), "f"(v.x), "f"(v.y));
}
__device__ __forceinline__ void stcs1(float* p, float v) {
    asm volatile("st.global.cs.f32 [%0], %1;" :: "l"(p), "f"(v));
}

#define SWZ128(off) ((off) ^ (((off) >> 3) & 0x70))

#define LDSM_X4(r, addr) \
    asm volatile("ldmatrix.sync.aligned.m8n8.x4.shared.b16 {%0,%1,%2,%3}, [%4];" \
        : "=r"((r)[0]), "=r"((r)[1]), "=r"((r)[2]), "=r"((r)[3]) : "r"(addr))
#define LDSM_X2(r, addr) \
    asm volatile("ldmatrix.sync.aligned.m8n8.x2.shared.b16 {%0,%1}, [%2];" \
        : "=r"((r)[0]), "=r"((r)[1]) : "r"(addr))
#define MMA_F16(d0,d1,d2,d3,a,b0,b1) \
    asm volatile("mma.sync.aligned.m16n8k16.row.col.f32.f16.f16.f32 " \
        "{%0,%1,%2,%3}, {%4,%5,%6,%7}, {%8,%9}, {%0,%1,%2,%3};" \
        : "+f"(d0), "+f"(d1), "+f"(d2), "+f"(d3) \
        : "r"((a)[0]), "r"((a)[1]), "r"((a)[2]), "r"((a)[3]), "r"(b0), "r"(b1))

// ---------------- layer-1 prep (f=3) ----------------
__global__ __launch_bounds__(128) void prep1_kernel(
    const float* __restrict__ x, const float* __restrict__ W,
    const float* __restrict__ b)
{
    __shared__ float sW[6*64];
    __shared__ float sb[64];
    int t = threadIdx.x;
    for (int i = t; i < 6*64; i += 128) sW[i] = W[i];
    if (t < 64) sb[t] = b[t];
    __syncthreads();
    int row = blockIdx.x * 128 + t;
    float x0 = x[row*3+0], x1 = x[row*3+1], x2 = x[row*3+2];
    float sq = x0*x0 + x1*x1 + x2*x2;
    g_xp[row] = make_float4(x0, x1, x2, sq);
    #pragma unroll 4
    for (int o = 0; o < 64; o++) {
        float s1 = x0*sW[0*64+o] + x1*sW[1*64+o] + x2*sW[2*64+o];
        float s2 = x0*sW[3*64+o] + x1*sW[4*64+o] + x2*sW[5*64+o];
        g_q[row*64+o] = s1 - s2 + sb[o];
        g_v[row*64+o] = s2;
    }
}

// ------- layers 2/3 prep: ReLU+BN on y -> xh/xl, sq, q, v (f=64) -------
template<int O>
__global__ __launch_bounds__(128) void prepbn_kernel(
    const float* __restrict__ W, const float* __restrict__ b)
{
    __shared__ float sW[128*O];
    __shared__ float sb[O];
    __shared__ float ssc[64], ssh[64];
    int t = threadIdx.x;
    for (int i = t; i < 128*O; i += 128) sW[i] = W[i];
    if (t < O) sb[t] = b[t];
    if (t < 64) { ssc[t] = g_scale[t]; ssh[t] = g_shift[t]; }
    __syncthreads();
    int row = blockIdx.x * 128 + t;
    float xr[64];
    float s = 0.f;
    #pragma unroll
    for (int f = 0; f < 64; f++) {
        float yy = g_y[(size_t)row*64 + f];
        float xn = ssc[f]*fmaxf(yy, 0.f) + ssh[f];
        xr[f] = xn;
        s += xn*xn;
        __half h = __float2half(xn);
        g_xh[(size_t)row*64 + f] = h;
        g_xl[(size_t)row*64 + f] = __float2half(xn - __half2float(h));
    }
    g_sq[row] = s;
    #pragma unroll 2
    for (int o = 0; o < O; o++) {
        float s1 = 0.f, s2 = 0.f;
        #pragma unroll
        for (int f = 0; f < 64; f++) {
            s1 += xr[f]*sW[f*O + o];
            s2 += xr[f]*sW[(64+f)*O + o];
        }
        g_q[(size_t)row*O + o] = s1 - s2 + sb[o];
        g_v[(size_t)row*O + o] = s2;
    }
}

// =============== symmetric tile distance kernel (layers 2/3) ===============
static constexpr uint32_t SOFF_AHI = 0;          // 16 KB (i-tile hi)
static constexpr uint32_t SOFF_ALO = 16384;      // 16 KB (i-tile lo)
static constexpr uint32_t SOFF_BHI = 32768;      // 16 KB (j-tile hi)
static constexpr uint32_t SOFF_BLO = 49152;      // 16 KB (j-tile lo)
static constexpr uint32_t SOFF_SQI = 65536;      // 512 B
static constexpr uint32_t SOFF_SQJ = 66048;      // 512 B
static constexpr int DSMEM_SYM     = 66560 + 1024;

template<int NK>   // k16 steps: 4 for f=64
__global__ __launch_bounds__(256, 3) void distsym_kernel(
    const __half* __restrict__ XH, const __half* __restrict__ XL,
    const float* __restrict__ SQ, float* __restrict__ D)
{
    extern __shared__ char smraw[];
    uint32_t sm0  = (uint32_t)__cvta_generic_to_shared(smraw);
    uint32_t base = (sm0 + 1023) & ~1023u;
    char* gen = smraw + (base - sm0);

    const int t = threadIdx.x;
    const int w = t >> 5;
    const int lane = t & 31;
    const int batch = blockIdx.y;

    int p = blockIdx.x, ti = 0;
    #pragma unroll 1
    while (p >= 32 - ti) { p -= 32 - ti; ti++; }
    const int tj = ti + p;
    const int i0 = ti * 128, j0 = tj * 128;
    const bool diag = (ti == tj);

    const __half* XHb = XH + (size_t)batch * NPTS * 64;
    const __half* XLb = XL + (size_t)batch * NPTS * 64;
    const float* SQb = SQ + batch * NPTS;
    float* Db = D + (size_t)batch * NPTS * NPTS;

    #pragma unroll
    for (int k = 0; k < 8; k++) {
        int idx = t + 256*k;
        int which = idx >> 10;
        int r = (idx >> 3) & 127;
        int c8 = idx & 7;
        uint32_t sw = SWZ128((uint32_t)(r*128 + c8*16));
        cpasync16(base + (which ? SOFF_ALO : SOFF_AHI) + sw,
                  (which ? XLb : XHb) + (size_t)(i0 + r)*64 + c8*8);
        cpasync16(base + (which ? SOFF_BLO : SOFF_BHI) + sw,
                  (which ? XLb : XHb) + (size_t)(j0 + r)*64 + c8*8);
    }
    if (t < 32) cpasync16(base + SOFF_SQI + t*16, SQb + i0 + t*4);
    else if (t < 64) cpasync16(base + SOFF_SQJ + (t-32)*16, SQb + j0 + (t-32)*4);
    cp_commit();
    cp_wait<0>();
    __syncthreads();

    uint32_t ahi[NK][4], alo[NK][4];
    {
        int arow = w*16 + (lane & 15);
        int acolb = (lane >> 4) * 16;
        #pragma unroll
        for (int ks = 0; ks < NK; ks++) {
            uint32_t off = (uint32_t)(arow*128 + ks*32 + acolb);
            LDSM_X4(ahi[ks], base + SOFF_AHI + SWZ128(off));
            LDSM_X4(alo[ks], base + SOFF_ALO + SWZ128(off));
        }
    }

    const int brl = lane & 15;
    const int rr = lane >> 2;
    const int irow  = i0 + w*16 + rr;
    const float* s_sqi = (const float*)(gen + SOFF_SQI);
    const float2* sqjp = (const float2*)(gen + SOFF_SQJ);
    const float sqi0 = s_sqi[w*16 + rr];
    const float sqi8 = s_sqi[w*16 + rr + 8];

    #pragma unroll
    for (int nb = 0; nb < 16; nb++) {
        float d0 = 0.f, d1 = 0.f, d2 = 0.f, d3 = 0.f;
        #pragma unroll
        for (int ks = 0; ks < NK; ks++) {
            uint32_t off = (uint32_t)((nb*8 + (brl & 7))*128 + ks*32
                                      + ((brl >> 3) & 1)*16);
            uint32_t bh[2], bl[2];
            LDSM_X2(bh, base + SOFF_BHI + SWZ128(off));
            LDSM_X2(bl, base + SOFF_BLO + SWZ128(off));
            MMA_F16(d0, d1, d2, d3, ahi[ks], bh[0], bh[1]);
            MMA_F16(d0, d1, d2, d3, ahi[ks], bl[0], bl[1]);
            MMA_F16(d0, d1, d2, d3, alo[ks], bh[0], bh[1]);
        }
        float2 sq2 = sqjp[nb*4 + (lane & 3)];
        int j = j0 + nb*8 + 2*(lane & 3);
        float2 o0, o1;
        o0.x = fmaf(d0, -2.f, sq2.x); o0.y = fmaf(d1, -2.f, sq2.y);
        o1.x = fmaf(d2, -2.f, sq2.x); o1.y = fmaf(d3, -2.f, sq2.y);
        stcs2(&Db[(size_t)irow*NPTS + j], o0);
        stcs2(&Db[(size_t)(irow + 8)*NPTS + j], o1);
        if (!diag) {
            stcs1(&Db[(size_t)j*NPTS + irow],           fmaf(d0, -2.f, sqi0));
            stcs1(&Db[(size_t)(j+1)*NPTS + irow],       fmaf(d1, -2.f, sqi0));
            stcs1(&Db[(size_t)j*NPTS + irow + 8],       fmaf(d2, -2.f, sqi8));
            stcs1(&Db[(size_t)(j+1)*NPTS + irow + 8],   fmaf(d3, -2.f, sqi8));
        }
    }
}

// ====== layer-1 fused select: on-the-fly f=3 keys + exact top-32 + gather ======
template<int O>
__global__ __launch_bounds__(256) void select1_kernel(
    const float4* __restrict__ XP, const float* __restrict__ V,
    const float* __restrict__ Q, float* __restrict__ OUT)
{
    const int wid = threadIdx.x >> 5;
    const int lane = threadIdx.x & 31;
    const int row = blockIdx.x * 8 + wid;          // 0..32767
    const int b = row >> 12;
    const float4* XPb = XP + b * NPTS;

    float4 xi = __ldg(&XPb[row & 4095]);
    const float a0 = -2.f * xi.x, a1 = -2.f * xi.y, a2 = -2.f * xi.z;

    float thr = INFINITY;
    unsigned svalu = 0xFF800000u;   // ordf(+inf)
    int sidx = 0, vlane = 0;

    for (int it = 0; it < 8; it++) {
        #pragma unroll
        for (int q = 0; q < 4; q++) {
            const int jb0 = it*512 + q*128;
            float4 p0 = __ldg(&XPb[jb0 + 4*lane + 0]);
            float4 p1 = __ldg(&XPb[jb0 + 4*lane + 1]);
            float4 p2 = __ldg(&XPb[jb0 + 4*lane + 2]);
            float4 p3 = __ldg(&XPb[jb0 + 4*lane + 3]);
            float4 vv;
            vv.x = fmaf(a0, p0.x, fmaf(a1, p0.y, fmaf(a2, p0.z, p0.w)));
            vv.y = fmaf(a0, p1.x, fmaf(a1, p1.y, fmaf(a2, p1.z, p1.w)));
            vv.z = fmaf(a0, p2.x, fmaf(a1, p2.y, fmaf(a2, p2.z, p2.w)));
            vv.w = fmaf(a0, p3.x, fmaf(a1, p3.y, fmaf(a2, p3.z, p3.w)));
            float rmin = fminf(fminf(vv.x, vv.y), fminf(vv.z, vv.w));
            if (__ballot_sync(FULLMASK, rmin < thr)) {
                #pragma unroll
                for (int s = 0; s < 4; s++) {
                    float key = (s==0) ? vv.x : (s==1) ? vv.y : (s==2) ? vv.z : vv.w;
                    unsigned m = __ballot_sync(FULLMASK, key < thr);
                    while (m) {
                        int src = __ffs(m) - 1; m &= m - 1;
                        float kc = __shfl_sync(FULLMASK, key, src);
                        if (kc < thr) {
                            if (lane == vlane) { svalu = ordf(kc); sidx = jb0 + src*4 + s; }
                            unsigned tu = __reduce_max_sync(FULLMASK, svalu);
                            vlane = __ffs(__ballot_sync(FULLMASK, svalu == tu)) - 1;
                            thr = iordf(tu);
                        }
                    }
                }
            }
        }
    }

    const int bb = b * NPTS;
    float m0 = -INFINITY, m1 = -INFINITY;
    #pragma unroll 4
    for (int s = 0; s < 32; s++) {
        int js = __shfl_sync(FULLMASK, sidx, s);
        const float* vp = V + (size_t)(bb + js) * 64;
        m0 = fmaxf(m0, vp[lane]);
        m1 = fmaxf(m1, vp[lane + 32]);
    }
    OUT[(size_t)row*64 + lane]      = Q[(size_t)row*64 + lane] + m0;
    OUT[(size_t)row*64 + lane + 32] = Q[(size_t)row*64 + lane + 32] + m1;
}

// ====== warp-per-row exact top-32 streaming select + v-gather (layers 2/3) ======
template<int O>
__global__ __launch_bounds__(256) void select_kernel(
    const float* __restrict__ D, const float* __restrict__ V,
    const float* __restrict__ Q, float* __restrict__ OUT)
{
    const int wid = threadIdx.x >> 5;
    const int lane = threadIdx.x & 31;
    const int row = blockIdx.x * 8 + wid;          // 0..32767
    const int b = row >> 12;
    const float4* Drow = (const float4*)(D + (size_t)b*NPTS*NPTS
                                           + (size_t)(row & 4095)*NPTS);

    float thr = INFINITY;
    unsigned svalu = 0xFF800000u;   // ordf(+inf)
    int sidx = 0, vlane = 0;

    for (int it = 0; it < 8; it++) {
        float4 vq[4];
        #pragma unroll
        for (int q = 0; q < 4; q++) vq[q] = ldcs4(&Drow[it*128 + q*32 + lane]);
        #pragma unroll
        for (int q = 0; q < 4; q++) {
            float4 vv = vq[q];
            const int jb0 = it*512 + q*128;
            float rmin = fminf(fminf(vv.x, vv.y), fminf(vv.z, vv.w));
            if (__ballot_sync(FULLMASK, rmin < thr)) {
                #pragma unroll
                for (int s = 0; s < 4; s++) {
                    float key = (s==0) ? vv.x : (s==1) ? vv.y : (s==2) ? vv.z : vv.w;
                    unsigned m = __ballot_sync(FULLMASK, key < thr);
                    while (m) {
                        int src = __ffs(m) - 1; m &= m - 1;
                        float kc = __shfl_sync(FULLMASK, key, src);
                        if (kc < thr) {
                            if (lane == vlane) { svalu = ordf(kc); sidx = jb0 + src*4 + s; }
                            unsigned tu = __reduce_max_sync(FULLMASK, svalu);
                            vlane = __ffs(__ballot_sync(FULLMASK, svalu == tu)) - 1;
                            thr = iordf(tu);
                        }
                    }
                }
            }
        }
    }

    const int bb = b * NPTS;
    if (O == 64) {
        float m0 = -INFINITY, m1 = -INFINITY;
        #pragma unroll 4
        for (int s = 0; s < 32; s++) {
            int js = __shfl_sync(FULLMASK, sidx, s);
            const float* vp = V + (size_t)(bb + js) * 64;
            m0 = fmaxf(m0, vp[lane]);
            m1 = fmaxf(m1, vp[lane + 32]);
        }
        OUT[(size_t)row*64 + lane]      = Q[(size_t)row*64 + lane] + m0;
        OUT[(size_t)row*64 + lane + 32] = Q[(size_t)row*64 + lane + 32] + m1;
    } else {
        float m0 = -INFINITY;
        for (int s = 0; s < 32; s++) {
            int js = __shfl_sync(FULLMASK, sidx, s);
            if (lane < O) m0 = fmaxf(m0, V[(size_t)(bb + js) * O + lane]);
        }
        if (lane < O) OUT[(size_t)row*O + lane] = Q[(size_t)row*O + lane] + m0;
    }
}

// ---------------- BN stats ----------------
__global__ __launch_bounds__(256) void bnred_kernel()
{
    __shared__ float ps[256], pss[256];
    int t = threadIdx.x, c = t & 63, g = t >> 6;
    int row0 = blockIdx.x * 128;
    float s = 0.f, ss = 0.f;
    for (int r = g; r < 128; r += 4) {
        float a = fmaxf(g_y[(size_t)(row0+r)*64 + c], 0.f);
        s += a; ss += a*a;
    }
    ps[t] = s; pss[t] = ss;
    __syncthreads();
    if (t < 64) {
        g_part[blockIdx.x*64 + t]   = ps[t]  + ps[t+64]  + ps[t+128]  + ps[t+192];
        g_partsq[blockIdx.x*64 + t] = pss[t] + pss[t+64] + pss[t+128] + pss[t+192];
    }
}

__global__ __launch_bounds__(512) void bnfin_kernel(
    const float* __restrict__ gamma, const float* __restrict__ beta)
{
    __shared__ float s1[512], s2[512];
    int t = threadIdx.x, c = t & 63, g = t >> 6;   // g in 0..7
    float s = 0.f, ss = 0.f;
    for (int p = g; p < 256; p += 8) { s += g_part[p*64 + c]; ss += g_partsq[p*64 + c]; }
    s1[t] = s; s2[t] = ss;
    __syncthreads();
    if (t < 64) {
        float S = 0.f, SS = 0.f;
        #pragma unroll
        for (int k = 0; k < 8; k++) { S += s1[t + 64*k]; SS += s2[t + 64*k]; }
        const float inv = 1.f / 32768.f;
        float mean = S * inv;
        float var = SS * inv - mean*mean;
        if (var < 0.f) var = 0.f;
        float sc = gamma[t] * rsqrtf(var + 1e-5f);
        g_scale[t] = sc;
        g_shift[t] = beta[t] - mean*sc;
    }
}

// ---------------- loss ----------------
__global__ __launch_bounds__(256) void lossred_kernel(
    const float* __restrict__ h, const float* __restrict__ tgt)
{
    __shared__ float ps[256];
    int t = threadIdx.x;
    int base = blockIdx.x * 1024;
    float s = 0.f;
    for (int k = t; k < 1024; k += 256) {
        float d = h[base + k] - tgt[base + k];
        s += d*d;
    }
    ps[t] = s; __syncthreads();
    for (int off = 128; off > 0; off >>= 1) {
        if (t < off) ps[t] += ps[t + off];
        __syncthreads();
    }
    if (t == 0) g_lpart[blockIdx.x] = ps[0];
}

__global__ __launch_bounds__(128) void lossfin_kernel(float* __restrict__ out_loss)
{
    __shared__ float buf[128];
    int t = threadIdx.x;
    buf[t] = (t < 96) ? g_lpart[t] : 0.f;
    __syncthreads();
    for (int off = 64; off > 0; off >>= 1) {
        if (t < off) buf[t] += buf[t + off];
        __syncthreads();
    }
    if (t == 0) *out_loss = buf[0] / 98304.0f;
}

// ---------------- driver ----------------
extern "C" void kernel_launch(void* const* d_in, const int* in_sizes, int n_in,
                              void* d_out, int out_size)
{
    const float* x   = (const float*)d_in[0];
    const float* tgt = (const float*)d_in[1];
    const float* W1  = (const float*)d_in[2];
    const float* b1  = (const float*)d_in[3];
    const float* g1  = (const float*)d_in[4];
    const float* be1 = (const float*)d_in[5];
    const float* W2  = (const float*)d_in[6];
    const float* b2  = (const float*)d_in[7];
    const float* g2  = (const float*)d_in[8];
    const float* be2 = (const float*)d_in[9];
    const float* W3  = (const float*)d_in[10];
    const float* b3  = (const float*)d_in[11];
    float* out = (float*)d_out;

    float *p_D, *p_sq, *p_q, *p_v, *p_y;
    float4* p_xp;
    __half *p_xh, *p_xl;
    cudaGetSymbolAddress((void**)&p_D,  g_D);
    cudaGetSymbolAddress((void**)&p_xp, g_xp);
    cudaGetSymbolAddress((void**)&p_sq, g_sq);
    cudaGetSymbolAddress((void**)&p_q,  g_q);
    cudaGetSymbolAddress((void**)&p_v,  g_v);
    cudaGetSymbolAddress((void**)&p_y,  g_y);
    cudaGetSymbolAddress((void**)&p_xh, g_xh);
    cudaGetSymbolAddress((void**)&p_xl, g_xl);

    cudaFuncSetAttribute(distsym_kernel<4>,
                         cudaFuncAttributeMaxDynamicSharedMemorySize, DSMEM_SYM);

    dim3 sgrid(528, NB);

    // ----- layer 1 (f=3 -> 64): no D materialization, keys on the fly -----
    prep1_kernel<<<256, 128>>>(x, W1, b1);
    select1_kernel<64><<<4096, 256>>>(p_xp, p_v, p_q, p_y);
    bnred_kernel<<<256, 256>>>();
    bnfin_kernel<<<1, 512>>>(g1, be1);

    // ----- layer 2 (f=64 -> 64) -----
    prepbn_kernel<64><<<256, 128>>>(W2, b2);
    distsym_kernel<4><<<sgrid, 256, DSMEM_SYM>>>(p_xh, p_xl, p_sq, p_D);
    select_kernel<64><<<4096, 256>>>(p_D, p_v, p_q, p_y);
    bnred_kernel<<<256, 256>>>();
    bnfin_kernel<<<1, 512>>>(g2, be2);

    // ----- layer 3 (f=64 -> 3), h straight to d_out -----
    prepbn_kernel<3><<<256, 128>>>(W3, b3);
    distsym_kernel<4><<<sgrid, 256, DSMEM_SYM>>>(p_xh, p_xl, p_sq, p_D);
    select_kernel<3><<<4096, 256>>>(p_D, p_v, p_q, out);

    // ----- loss -----
    lossred_kernel<<<96, 256>>>(out, tgt);
    lossfin_kernel<<<1, 128>>>(out + (out_size - 1));
}